// round 15
// baseline (speedup 1.0000x reference)
#include <cuda_runtime.h>
#include <math.h>

// Problem constants (fixed by setup_inputs)
#define BSZ   16
#define QN    900
#define CN    80
#define TN    1600
#define GS    3
#define NQ    (BSZ * QN)        // 14400
#define NROWS (NQ / GS)         // 4800 output rows
#define RPB   (QN / GS)         // 300 rows per batch

// Scratch (allocation-free rule: __device__ globals)
__device__ float  g_cc[NQ * CN];   // 2x focal class cost table [N, C] (labels = fast axis)
__device__ float4 g_q2[NQ * 2];    // per-query:  [5cx,5cy,5w,5h][5x0,5y0,5x1,5y1]
__device__ float4 g_t2[TN * 2];    // per-target: [5cx,5cy,5w,5h][5x0,5y0,5x1,5y1]
__device__ int    g_tlab[TN];      // target labels

__device__ __forceinline__ float focal_cc2(float x) {
    float p   = 1.f / (1.f + __expf(-x));
    float om  = 1.f - p;
    float pos = 0.5f * om * om * (-__logf(p + 1e-8f));   // 2 * 0.25
    float neg = 1.5f * p  * p  * (-__logf(om + 1e-8f));  // 2 * 0.75
    return pos - neg;
}

// ---------------- fused prep ----------------
#define CCB 1125   // (NQ*CN/4)/256 blocks for the cc table
#define BXB 57     // ceil(NQ/256) blocks for boxes

__global__ __launch_bounds__(256) void prep_kernel(const float4* __restrict__ logits4,
                                                   const float*  __restrict__ qb,
                                                   const float*  __restrict__ tb,
                                                   const int*    __restrict__ tl) {
    int b = blockIdx.x;
    if (b < CCB) {
        int i = b * 256 + threadIdx.x;
        float4 x = logits4[i];
        float4 r;
        r.x = focal_cc2(x.x); r.y = focal_cc2(x.y);
        r.z = focal_cc2(x.z); r.w = focal_cc2(x.w);
        reinterpret_cast<float4*>(g_cc)[i] = r;
    } else {
        int i = (b - CCB) * 256 + threadIdx.x;
        if (i < NQ) {
            float cx = qb[i*4+0], cy = qb[i*4+1], w = qb[i*4+2], h = qb[i*4+3];
            float x0 = cx - 0.5f*w, y0 = cy - 0.5f*h;
            float x1 = cx + 0.5f*w, y1 = cy + 0.5f*h;
            g_q2[i*2+0] = make_float4(5.f*cx, 5.f*cy, 5.f*w, 5.f*h);
            g_q2[i*2+1] = make_float4(5.f*x0, 5.f*y0, 5.f*x1, 5.f*y1);
        }
        if (i < TN) {
            float cx = tb[i*4+0], cy = tb[i*4+1], w = tb[i*4+2], h = tb[i*4+3];
            float x0 = cx - 0.5f*w, y0 = cy - 0.5f*h;
            float x1 = cx + 0.5f*w, y1 = cy + 0.5f*h;
            g_t2[i*2+0] = make_float4(5.f*cx, 5.f*cy, 5.f*w, 5.f*h);
            g_t2[i*2+1] = make_float4(5.f*x0, 5.f*y0, 5.f*x1, 5.f*y1);
            g_tlab[i]   = tl[i];
        }
    }
}

// ---------------- main: 2x2 tile, NO shared memory (uniform L1-hit LDGs) ----------------
#define THR  160     // 5 warps; block covers 320 adjacent columns
#define RCH  10      // output rows per block; 30 queries; grid = 5 x 480 = 2400 blocks

__device__ __forceinline__ float rcp_approx(float x) {
    float r; asm("rcp.approx.f32 %0, %1;" : "=f"(r) : "f"(x)); return r;
}

// All coords 5x-scaled, areas 25x; GIoU ratios are scale-invariant.
__device__ __forceinline__ float pair_cost(const float4 qA, const float4 qB, const float qar,
                                           const float4 tA, const float4 tB, const float tar,
                                           const float cc2) {
    // L1 (x5 pre-scaled; weight folded)
    float l1 = fabsf(qA.x - tA.x) + fabsf(qA.y - tA.y)
             + fabsf(qA.z - tA.z) + fabsf(qA.w - tA.w);
    // intersection (5x coords -> 25x areas)
    float ltx = fmaxf(qB.x, tB.x), lty = fmaxf(qB.y, tB.y);
    float rbx = fminf(qB.z, tB.z), rby = fminf(qB.w, tB.w);
    float dx = rbx - ltx,          dy = rby - lty;
    float wx = fmaxf(dx, 0.f),     wy = fmaxf(dy, 0.f);
    float inter = wx * wy;
    float uni = (qar + tar) - inter;
    // enclosing box: ewx = 5qw + 5tw - dx  (max(a,b) = a+b-min(a,b))
    float ewx = (qA.z + tA.z) - dx;
    float ewy = (qA.w + tA.w) - dy;
    float earea = ewx * ewy;
    // cost = l1 + cc2 + 2*(1 - uni/earea - inter/uni)
    float ru = rcp_approx(uni);
    float re = rcp_approx(earea);
    float s  = __fmaf_rn(-uni,   re, 1.0f);
    s        = __fmaf_rn(-inter, ru, s);
    return __fmaf_rn(2.f, s, l1 + cc2);
}

__global__ __launch_bounds__(THR) void cost_kernel(float* __restrict__ out) {
    const int t0 = (blockIdx.x * THR + threadIdx.x) * 2;   // adjacent target columns t0, t0+1
    const int r0 = blockIdx.y * RCH;                       // first output row of this chunk
    const int nstart = (r0 / RPB) * QN + (r0 % RPB) * GS;  // 300 % RCH == 0: no batch crossing

    // target data -> registers (held for the whole chunk)
    const float4 tA0 = __ldg(&g_t2[t0*2+0]), tB0 = __ldg(&g_t2[t0*2+1]);
    const float4 tA1 = __ldg(&g_t2[t0*2+2]), tB1 = __ldg(&g_t2[t0*2+3]);
    const float  tar0 = tA0.z * tA0.w;     // 25 * area
    const float  tar1 = tA1.z * tA1.w;
    const float* ccp0 = g_cc + nstart * CN + __ldg(&g_tlab[t0]);
    const float* ccp1 = g_cc + nstart * CN + __ldg(&g_tlab[t0+1]);

    const float4* qp = g_q2 + nstart * 2;  // warp-uniform, L1-resident after first touch
    float* op = out + (size_t)r0 * TN + t0;

    #pragma unroll 1
    for (int rp = 0; rp < RCH / 2; rp++) {           // two adjacent output rows per iteration
        float m00, m01, m10, m11;
        #pragma unroll
        for (int g = 0; g < GS; g++) {
            // row A queries: qp[2g..], row B queries: qp[2(g+3)..]  (uniform LDG.128)
            const float4 aA = __ldg(qp + g*2 + 0);
            const float4 aB = __ldg(qp + g*2 + 1);
            const float4 bA = __ldg(qp + (g+3)*2 + 0);
            const float4 bB = __ldg(qp + (g+3)*2 + 1);
            const float  aar = aA.z * aA.w;          // 25 * area (≈ ref area, tol 1e-3)
            const float  bar = bA.z * bA.w;
            const float cc00 = __ldg(ccp0 + g * CN);
            const float cc01 = __ldg(ccp1 + g * CN);
            const float cc10 = __ldg(ccp0 + (g+3) * CN);
            const float cc11 = __ldg(ccp1 + (g+3) * CN);

            // 4 independent dependency chains
            float c00 = pair_cost(aA, aB, aar, tA0, tB0, tar0, cc00);
            float c01 = pair_cost(aA, aB, aar, tA1, tB1, tar1, cc01);
            float c10 = pair_cost(bA, bB, bar, tA0, tB0, tar0, cc10);
            float c11 = pair_cost(bA, bB, bar, tA1, tB1, tar1, cc11);
            if (g == 0) { m00 = c00; m01 = c01; m10 = c10; m11 = c11; }
            else {
                m00 = fmaxf(m00, c00); m01 = fmaxf(m01, c01);
                m10 = fmaxf(m10, c10); m11 = fmaxf(m11, c11);
            }
        }
        *reinterpret_cast<float2*>(op)      = make_float2(m00, m01);
        *reinterpret_cast<float2*>(op + TN) = make_float2(m10, m11);
        op   += 2 * TN;
        qp   += 12;            // 6 queries * 2 float4
        ccp0 += 6 * CN;
        ccp1 += 6 * CN;
    }
}

extern "C" void kernel_launch(void* const* d_in, const int* in_sizes, int n_in,
                              void* d_out, int out_size) {
    const float* logits  = (const float*)d_in[0];  // [16,900,80]
    const float* pboxes  = (const float*)d_in[1];  // [16,900,4]
    const int*   tlabels = (const int*)  d_in[2];  // [1600]
    const float* tboxes  = (const float*)d_in[3];  // [1600,4]
    (void)in_sizes; (void)n_in; (void)out_size;

    prep_kernel<<<CCB + BXB, 256>>>((const float4*)logits, pboxes, tboxes, tlabels);
    cost_kernel<<<dim3(800 / THR, NROWS / RCH), THR>>>((float*)d_out);
}

// round 16
// speedup vs baseline: 1.0944x; 1.0944x over previous
#include <cuda_runtime.h>
#include <math.h>

// Problem constants (fixed by setup_inputs)
#define BSZ   16
#define QN    900
#define CN    80
#define TN    1600
#define GS    3
#define NQ    (BSZ * QN)        // 14400
#define NROWS (NQ / GS)         // 4800 output rows
#define RPB   (QN / GS)         // 300 rows per batch

// Scratch (allocation-free rule: __device__ globals)
__device__ float  g_cc[NQ * CN];            // 2x focal class cost table [N, C]
__device__ float4 g_qd[NQ * 3];             // per-query:  [5cx,5cy,5w,5h][x0,y0,x1,y1][area,w,h,-]
__device__ float4 g_td[TN * 3];             // per-target: [5cx,5cy,5w,5h][x0,y0,x1,y1][area,w,h,label]

__device__ __forceinline__ float focal_cc2(float x) {
    float p   = 1.f / (1.f + __expf(-x));
    float om  = 1.f - p;
    float pos = 0.5f * om * om * (-__logf(p + 1e-8f));   // 2 * 0.25
    float neg = 1.5f * p  * p  * (-__logf(om + 1e-8f));  // 2 * 0.75
    return pos - neg;
}

// ---------------- fused prep ----------------
#define CCB 1125   // (NQ*CN/4)/256 blocks for the cc table
#define BXB 57     // ceil(NQ/256) blocks for boxes

__global__ __launch_bounds__(256) void prep_kernel(const float4* __restrict__ logits4,
                                                   const float*  __restrict__ qb,
                                                   const float*  __restrict__ tb,
                                                   const int*    __restrict__ tl) {
    int b = blockIdx.x;
    if (b < CCB) {
        int i = b * 256 + threadIdx.x;
        float4 x = logits4[i];
        float4 r;
        r.x = focal_cc2(x.x); r.y = focal_cc2(x.y);
        r.z = focal_cc2(x.z); r.w = focal_cc2(x.w);
        reinterpret_cast<float4*>(g_cc)[i] = r;
    } else {
        int i = (b - CCB) * 256 + threadIdx.x;
        if (i < NQ) {
            float cx = qb[i*4+0], cy = qb[i*4+1], w = qb[i*4+2], h = qb[i*4+3];
            float x0 = cx - 0.5f*w, y0 = cy - 0.5f*h;
            float x1 = cx + 0.5f*w, y1 = cy + 0.5f*h;
            float ww = x1 - x0, hh = y1 - y0;
            float area = ww * hh;                       // same rounding path as reference
            g_qd[i*3+0] = make_float4(5.f*cx, 5.f*cy, 5.f*w, 5.f*h);
            g_qd[i*3+1] = make_float4(x0, y0, x1, y1);
            g_qd[i*3+2] = make_float4(area, ww, hh, 0.f);
        }
        if (i < TN) {
            float cx = tb[i*4+0], cy = tb[i*4+1], w = tb[i*4+2], h = tb[i*4+3];
            float x0 = cx - 0.5f*w, y0 = cy - 0.5f*h;
            float x1 = cx + 0.5f*w, y1 = cy + 0.5f*h;
            float ww = x1 - x0, hh = y1 - y0;
            float area = ww * hh;
            g_td[i*3+0] = make_float4(5.f*cx, 5.f*cy, 5.f*w, 5.f*h);
            g_td[i*3+1] = make_float4(x0, y0, x1, y1);
            g_td[i*3+2] = make_float4(area, ww, hh, __int_as_float(tl[i]));
        }
    }
}

// ---------------- main: fused cost + group-max, 2 columns per thread ----------------
#define THR  160     // 5 warps; thread covers columns t and t+800
#define RCH  10      // output rows per block (300 % 10 == 0; grid = 5 x 480 = 2400 blocks)

__device__ __forceinline__ float rcp_approx(float x) {
    float r;
    asm("rcp.approx.f32 %0, %1;" : "=f"(r) : "f"(x));
    return r;
}

__device__ __forceinline__ float pair_cost(const float4 qA, const float4 qB, const float4 qC,
                                           const float4 tA, const float4 tB, const float4 tC,
                                           const float cc2) {
    // L1 box cost (inputs pre-scaled by 5)
    float l1 = fabsf(qA.x - tA.x) + fabsf(qA.y - tA.y)
             + fabsf(qA.z - tA.z) + fabsf(qA.w - tA.w);
    // intersection
    float ltx = fmaxf(qB.x, tB.x), lty = fmaxf(qB.y, tB.y);
    float rbx = fminf(qB.z, tB.z), rby = fminf(qB.w, tB.w);
    float dx = rbx - ltx,          dy = rby - lty;
    float wx = fmaxf(dx, 0.f),     wy = fmaxf(dy, 0.f);
    float inter = wx * wy;
    float uni = (qC.x + tC.x) - inter;
    // enclosing box via max(a,b) = a+b-min(a,b):  ewx = qw + tw - dx
    float ewx = (qC.y + tC.y) - dx;
    float ewy = (qC.z + tC.z) - dy;
    float earea = ewx * ewy;
    // cost = l1(x5) + cc(x2) + 2*(1 - uni/earea - inter/uni)
    float ru = rcp_approx(uni);
    float re = rcp_approx(earea);
    float s  = __fmaf_rn(-uni,   re, 1.0f);
    s        = __fmaf_rn(-inter, ru, s);
    return __fmaf_rn(2.f, s, l1 + cc2);
}

__global__ __launch_bounds__(THR) void cost_kernel(float* __restrict__ out) {
    __shared__ float4 shq[RCH * 3 * 3];              // 30 queries x 3 float4 = 1.44 KB

    const int t0 = blockIdx.x * THR + threadIdx.x;   // first target column (< 800)
    const int t1 = t0 + 800;                         // second target column
    const int r0 = blockIdx.y * RCH;                 // first output row of this chunk
    const int nstart = (r0 / RPB) * QN + (r0 % RPB) * GS;

    if (threadIdx.x < RCH * 9) shq[threadIdx.x] = g_qd[nstart * 3 + threadIdx.x];
    __syncthreads();

    // target data -> registers (held for the whole chunk)
    const float4 tA0 = g_td[t0*3+0], tB0 = g_td[t0*3+1], tC0 = g_td[t0*3+2];
    const float4 tA1 = g_td[t1*3+0], tB1 = g_td[t1*3+1], tC1 = g_td[t1*3+2];
    const float* ccp0 = g_cc + nstart * CN + __float_as_int(tC0.w);
    const float* ccp1 = g_cc + nstart * CN + __float_as_int(tC1.w);

    float* op = out + (size_t)r0 * TN + t0;

    #pragma unroll 2
    for (int rr = 0; rr < RCH; rr++) {
        float m0, m1;
        #pragma unroll
        for (int g = 0; g < GS; g++) {
            const float4 qA = shq[(rr*3 + g)*3 + 0];
            const float4 qB = shq[(rr*3 + g)*3 + 1];
            const float4 qC = shq[(rr*3 + g)*3 + 2];
            const float cc0 = __ldg(ccp0 + g * CN);
            const float cc1 = __ldg(ccp1 + g * CN);
            float c0 = pair_cost(qA, qB, qC, tA0, tB0, tC0, cc0);
            float c1 = pair_cost(qA, qB, qC, tA1, tB1, tC1, cc1);
            if (g == 0) { m0 = c0; m1 = c1; }
            else        { m0 = fmaxf(m0, c0); m1 = fmaxf(m1, c1); }
        }
        op[0]   = m0;
        op[800] = m1;
        op += TN;
        ccp0 += GS * CN;
        ccp1 += GS * CN;
    }
}

extern "C" void kernel_launch(void* const* d_in, const int* in_sizes, int n_in,
                              void* d_out, int out_size) {
    const float* logits  = (const float*)d_in[0];  // [16,900,80]
    const float* pboxes  = (const float*)d_in[1];  // [16,900,4]
    const int*   tlabels = (const int*)  d_in[2];  // [1600]
    const float* tboxes  = (const float*)d_in[3];  // [1600,4]
    (void)in_sizes; (void)n_in; (void)out_size;

    prep_kernel<<<CCB + BXB, 256>>>((const float4*)logits, pboxes, tboxes, tlabels);
    cost_kernel<<<dim3(800 / THR, NROWS / RCH), THR>>>((float*)d_out);
}

// round 17
// speedup vs baseline: 1.1482x; 1.0492x over previous
#include <cuda_runtime.h>
#include <math.h>

// Problem constants (fixed by setup_inputs)
#define BSZ   16
#define QN    900
#define CN    80
#define TN    1600
#define GS    3
#define NQ    (BSZ * QN)        // 14400
#define NROWS (NQ / GS)         // 4800 output rows
#define RPB   (QN / GS)         // 300 rows per batch

// Scratch (allocation-free rule: __device__ globals)
__device__ float  g_cc[NQ * CN];   // 2x focal class cost table [N, C] (labels = fast axis)
__device__ float4 g_q2[NQ * 2];    // per-query:  [5cx,5cy,5w,5h][5x0,5y0,5x1,5y1]
__device__ float4 g_t2[TN * 2];    // per-target: [5cx,5cy,5w,5h][5x0,5y0,5x1,5y1]
__device__ int    g_tlab[TN];      // target labels

__device__ __forceinline__ float focal_cc2(float x) {
    float p   = 1.f / (1.f + __expf(-x));
    float om  = 1.f - p;
    float pos = 0.5f * om * om * (-__logf(p + 1e-8f));   // 2 * 0.25
    float neg = 1.5f * p  * p  * (-__logf(om + 1e-8f));  // 2 * 0.75
    return pos - neg;
}

// ---------------- fused prep ----------------
#define CCB 1125   // (NQ*CN/4)/256 blocks for the cc table
#define BXB 57     // ceil(NQ/256) blocks for boxes

__global__ __launch_bounds__(256) void prep_kernel(const float4* __restrict__ logits4,
                                                   const float*  __restrict__ qb,
                                                   const float*  __restrict__ tb,
                                                   const int*    __restrict__ tl) {
    int b = blockIdx.x;
    if (b < CCB) {
        int i = b * 256 + threadIdx.x;
        float4 x = logits4[i];
        float4 r;
        r.x = focal_cc2(x.x); r.y = focal_cc2(x.y);
        r.z = focal_cc2(x.z); r.w = focal_cc2(x.w);
        reinterpret_cast<float4*>(g_cc)[i] = r;
    } else {
        int i = (b - CCB) * 256 + threadIdx.x;
        if (i < NQ) {
            float cx = qb[i*4+0], cy = qb[i*4+1], w = qb[i*4+2], h = qb[i*4+3];
            float x0 = cx - 0.5f*w, y0 = cy - 0.5f*h;
            float x1 = cx + 0.5f*w, y1 = cy + 0.5f*h;
            g_q2[i*2+0] = make_float4(5.f*cx, 5.f*cy, 5.f*w, 5.f*h);
            g_q2[i*2+1] = make_float4(5.f*x0, 5.f*y0, 5.f*x1, 5.f*y1);
        }
        if (i < TN) {
            float cx = tb[i*4+0], cy = tb[i*4+1], w = tb[i*4+2], h = tb[i*4+3];
            float x0 = cx - 0.5f*w, y0 = cy - 0.5f*h;
            float x1 = cx + 0.5f*w, y1 = cy + 0.5f*h;
            g_t2[i*2+0] = make_float4(5.f*cx, 5.f*cy, 5.f*w, 5.f*h);
            g_t2[i*2+1] = make_float4(5.f*x0, 5.f*y0, 5.f*x1, 5.f*y1);
            g_tlab[i]   = tl[i];
        }
    }
}

// ---------------- main: R3 skeleton + 2-float4 queries + single-rcp GIoU ----------------
#define THR  160     // 5 warps; thread covers columns t and t+800
#define RCH  10      // output rows per block (300 % 10 == 0; grid = 5 x 480 = 2400 blocks)
#define NQC  (RCH * GS)   // 30 queries per chunk

__device__ __forceinline__ float rcp_approx(float x) {
    float r;
    asm("rcp.approx.f32 %0, %1;" : "=f"(r) : "f"(x));
    return r;
}

// All coords 5x-scaled, areas 25x; GIoU ratios are scale-invariant.
__device__ __forceinline__ float pair_cost(const float4 qA, const float4 qB, const float qar,
                                           const float4 tA, const float4 tB, const float tar,
                                           const float cc2) {
    // L1 (x5 pre-scaled; weight folded)
    float l1 = fabsf(qA.x - tA.x) + fabsf(qA.y - tA.y)
             + fabsf(qA.z - tA.z) + fabsf(qA.w - tA.w);
    // intersection (5x coords -> 25x areas)
    float ltx = fmaxf(qB.x, tB.x), lty = fmaxf(qB.y, tB.y);
    float rbx = fminf(qB.z, tB.z), rby = fminf(qB.w, tB.w);
    float dx = rbx - ltx,          dy = rby - lty;
    float wx = fmaxf(dx, 0.f),     wy = fmaxf(dy, 0.f);
    float inter = wx * wy;
    float uni = (qar + tar) - inter;
    // enclosing box: ewx = 5qw + 5tw - dx  (max(a,b) = a+b-min(a,b))
    float ewx = (qA.z + tA.z) - dx;
    float ewy = (qA.w + tA.w) - dy;
    float earea = ewx * ewy;
    // s = 1 - (uni/earea + inter/uni) = 1 - (uni^2 + inter*earea) / (uni*earea)
    float r   = rcp_approx(uni * earea);                  // single MUFU.RCP
    float num = __fmaf_rn(inter, earea, uni * uni);
    float s   = __fmaf_rn(-num, r, 1.0f);
    // cost = l1 + cc2 + 2*s
    return __fmaf_rn(2.f, s, l1 + cc2);
}

__global__ __launch_bounds__(THR) void cost_kernel(float* __restrict__ out) {
    __shared__ float4 shq[NQC * 2];                  // 30 queries x 2 float4 = 960 B

    const int t0 = blockIdx.x * THR + threadIdx.x;   // first target column (< 800)
    const int t1 = t0 + 800;                         // second target column
    const int r0 = blockIdx.y * RCH;                 // first output row of this chunk
    const int nstart = (r0 / RPB) * QN + (r0 % RPB) * GS;

    if (threadIdx.x < NQC * 2) shq[threadIdx.x] = g_q2[nstart * 2 + threadIdx.x];
    __syncthreads();

    // target data -> registers (held for the whole chunk)
    const float4 tA0 = g_t2[t0*2+0], tB0 = g_t2[t0*2+1];
    const float4 tA1 = g_t2[t1*2+0], tB1 = g_t2[t1*2+1];
    const float  tar0 = tA0.z * tA0.w;               // 25 * area
    const float  tar1 = tA1.z * tA1.w;
    const float* ccp0 = g_cc + nstart * CN + g_tlab[t0];
    const float* ccp1 = g_cc + nstart * CN + g_tlab[t1];

    float* op = out + (size_t)r0 * TN + t0;
    const float4* qp = shq;

    #pragma unroll 2
    for (int rr = 0; rr < RCH; rr++) {
        float m0, m1;
        #pragma unroll
        for (int g = 0; g < GS; g++) {
            const float4 qA = qp[g*2 + 0];
            const float4 qB = qp[g*2 + 1];
            const float  qar = qA.z * qA.w;          // 25 * area (one FMUL replaces an LDS)
            const float cc0 = __ldg(ccp0 + g * CN);
            const float cc1 = __ldg(ccp1 + g * CN);
            float c0 = pair_cost(qA, qB, qar, tA0, tB0, tar0, cc0);
            float c1 = pair_cost(qA, qB, qar, tA1, tB1, tar1, cc1);
            if (g == 0) { m0 = c0; m1 = c1; }
            else        { m0 = fmaxf(m0, c0); m1 = fmaxf(m1, c1); }
        }
        op[0]   = m0;
        op[800] = m1;
        op   += TN;
        qp   += GS * 2;
        ccp0 += GS * CN;
        ccp1 += GS * CN;
    }
}

extern "C" void kernel_launch(void* const* d_in, const int* in_sizes, int n_in,
                              void* d_out, int out_size) {
    const float* logits  = (const float*)d_in[0];  // [16,900,80]
    const float* pboxes  = (const float*)d_in[1];  // [16,900,4]
    const int*   tlabels = (const int*)  d_in[2];  // [1600]
    const float* tboxes  = (const float*)d_in[3];  // [1600,4]
    (void)in_sizes; (void)n_in; (void)out_size;

    prep_kernel<<<CCB + BXB, 256>>>((const float4*)logits, pboxes, tboxes, tlabels);
    cost_kernel<<<dim3(800 / THR, NROWS / RCH), THR>>>((float*)d_out);
}